// round 17
// baseline (speedup 1.0000x reference)
#include <cuda_runtime.h>
#include <cuda_bf16.h>
#include <math.h>

// Problem constants
constexpr int Bn  = 4;
constexpr int Cn  = 256;
constexpr int Tn  = 4096;     // H*W
constexpr int CPGn = 8;       // channels per group (32 groups)

// Scratch (device globals; device-code use only — host-side use hands the GPU
// the ATS host-shadow address: the R3-R5 bug).
__device__ float g_scale[Bn * Cn];
__device__ float g_shift[Bn * Cn];
// bf16x2-packed buffers
__device__ unsigned g_xp[(size_t)Bn * 128 * Tn];          // [b][kt 8][t][16]  GN(x)
__device__ unsigned g_wq[768 * 128];                      // qkv_w packed [o][cp]
__device__ unsigned g_wp[256 * 128];                      // proj_w packed [o][cp]
__device__ unsigned g_qp[(size_t)Bn * 4 * 32 * Tn];       // [bh][cp][t] Q*0.125*log2e
__device__ unsigned g_kp[(size_t)Bn * 4 * Tn * 32];       // [bh][t][cp] (ldmatrix rows)
__device__ unsigned g_vp[(size_t)Bn * 4 * 64 * (Tn / 2)]; // [bh][c][sp] (ldmatrix rows)
__device__ unsigned g_ap[(size_t)Bn * 128 * Tn];          // [b][kt 8][t][16] attn out

// ---------------------------------------------------------------------------
__device__ __forceinline__ unsigned bf2(float lo, float hi) {
    unsigned r;
    asm("cvt.rn.satfinite.bf16x2.f32 %0, %1, %2;" : "=r"(r) : "f"(hi), "f"(lo));
    return r;
}
__device__ __forceinline__ float ex2(float x) {
    float r;
    asm("ex2.approx.ftz.f32 %0, %1;" : "=f"(r) : "f"(x));
    return r;
}

// m16n8k16 bf16 mma, fp32 accumulate (fragment maps validated R6-R16).
__device__ __forceinline__ void mma_bf16(float d[4],
                                         unsigned a0, unsigned a1,
                                         unsigned a2, unsigned a3,
                                         unsigned b0, unsigned b1) {
    asm volatile(
        "mma.sync.aligned.m16n8k16.row.col.f32.bf16.bf16.f32 "
        "{%0,%1,%2,%3}, {%4,%5,%6,%7}, {%8,%9}, {%0,%1,%2,%3};\n"
        : "+f"(d[0]), "+f"(d[1]), "+f"(d[2]), "+f"(d[3])
        : "r"(a0), "r"(a1), "r"(a2), "r"(a3), "r"(b0), "r"(b1));
}

__device__ __forceinline__ void ldsm4(unsigned* r, unsigned addr) {
    asm volatile("ldmatrix.sync.aligned.m8n8.x4.shared.b16 {%0,%1,%2,%3}, [%4];\n"
                 : "=r"(r[0]), "=r"(r[1]), "=r"(r[2]), "=r"(r[3]) : "r"(addr));
}
__device__ __forceinline__ void cpa16(unsigned dst, const void* src) {
    asm volatile("cp.async.cg.shared.global [%0], [%1], 16;\n"
                 :: "r"(dst), "l"(src));
}
__device__ __forceinline__ void cpa_commit() {
    asm volatile("cp.async.commit_group;\n");
}

// ---------------------------------------------------------------------------
// K1: GroupNorm statistics + fused coefficient write (float4 loads).
// ---------------------------------------------------------------------------
__global__ __launch_bounds__(256) void k_gn_stats(const float* __restrict__ x,
                                                  const float* __restrict__ gw,
                                                  const float* __restrict__ gb) {
    int bg = blockIdx.x;
    const float* base = x + (size_t)bg * CPGn * Tn;
    float s = 0.f, s2 = 0.f;
    #pragma unroll 4
    for (int i = threadIdx.x; i < CPGn * Tn / 4; i += 256) {
        float4 v = *(const float4*)(base + i * 4);
        s  += v.x + v.y + v.z + v.w;
        s2 += v.x * v.x + v.y * v.y + v.z * v.z + v.w * v.w;
    }
    #pragma unroll
    for (int m = 16; m; m >>= 1) {
        s  += __shfl_xor_sync(0xffffffffu, s,  m);
        s2 += __shfl_xor_sync(0xffffffffu, s2, m);
    }
    __shared__ float sh[16];
    int w = threadIdx.x >> 5;
    if ((threadIdx.x & 31) == 0) { sh[w] = s; sh[8 + w] = s2; }
    __syncthreads();
    if (threadIdx.x < 8) {
        s = 0.f; s2 = 0.f;
        #pragma unroll
        for (int i = 0; i < 8; i++) { s += sh[i]; s2 += sh[8 + i]; }
        const float n = (float)(CPGn * Tn);
        float mean = s / n;
        float var  = s2 / n - mean * mean;
        float rstd = rsqrtf(var + 1e-5f);
        int b = bg >> 5;
        int c = (bg & 31) * CPGn + threadIdx.x;
        float sc = rstd * gw[c];
        g_scale[b * Cn + c] = sc;
        g_shift[b * Cn + c] = gb[c] - mean * sc;
    }
}

// K1c: apply GN + pack X to bf16x2 in ldmatrix-row layout [b][kt][t][16].
// grid (Tn/128, 8, Bn), 256 threads; smem transpose keeps both sides coalesced.
__global__ __launch_bounds__(256) void k_gn_pack(const float* __restrict__ x) {
    __shared__ unsigned xs[128 * 20];        // [t][cpl] stride 20 (80B rows)
    int b = blockIdx.z, cc = blockIdx.y;
    int t0 = blockIdx.x * 128;
    #pragma unroll
    for (int r = 0; r < 2; r++) {
        int idx = threadIdx.x + r * 256;     // 512 tasks
        int cpl = idx >> 5, tq = (idx & 31) << 2;
        int c = cc * 32 + 2 * cpl;
        const float* p0 = x + ((size_t)b * Cn + c) * Tn + t0 + tq;
        float4 a = *(const float4*)p0;
        float4 bb = *(const float4*)(p0 + Tn);
        float s0 = g_scale[b * Cn + c],     h0 = g_shift[b * Cn + c];
        float s1 = g_scale[b * Cn + c + 1], h1 = g_shift[b * Cn + c + 1];
        xs[(tq + 0) * 20 + cpl] = bf2(fmaf(a.x, s0, h0), fmaf(bb.x, s1, h1));
        xs[(tq + 1) * 20 + cpl] = bf2(fmaf(a.y, s0, h0), fmaf(bb.y, s1, h1));
        xs[(tq + 2) * 20 + cpl] = bf2(fmaf(a.z, s0, h0), fmaf(bb.z, s1, h1));
        xs[(tq + 3) * 20 + cpl] = bf2(fmaf(a.w, s0, h0), fmaf(bb.w, s1, h1));
    }
    __syncthreads();
    #pragma unroll
    for (int r = 0; r < 2; r++) {
        int idx = threadIdx.x + r * 256;     // 512 uint4 tasks
        int row = idx >> 2, m = idx & 3;
        uint4 v = *(uint4*)&xs[row * 20 + m * 4];
        *(uint4*)(g_xp + (((size_t)b * 8 + cc) * Tn + t0 + row) * 16 + m * 4) = v;
    }
}

// K1d: pack BOTH weight matrices in one launch
__global__ __launch_bounds__(128) void k_wpack(const float* __restrict__ Wq,
                                               const float* __restrict__ Wp) {
    int o = blockIdx.x, cp = threadIdx.x;
    if (o < 768) {
        float2 w = *(const float2*)(Wq + (size_t)o * Cn + 2 * cp);
        g_wq[(size_t)o * 128 + cp] = bf2(w.x, w.y);
    } else {
        int o2 = o - 768;
        float2 w = *(const float2*)(Wp + (size_t)o2 * Cn + 2 * cp);
        g_wp[(size_t)o2 * 128 + cp] = bf2(w.x, w.y);
    }
}

// ---------------------------------------------------------------------------
// Packed-operand GEMM body: B-fragments via ldmatrix from [kt][t][16] rows.
// Block 64(o) x 128(t), K-tile 32 floats (16 words). 8 warps (4M x 2N).
// X smem rows 80B (stride 20 words): conflict-free cp.async + ldsm phases.
// ---------------------------------------------------------------------------
template <bool VSPLIT>
__device__ __forceinline__ void gemm_body_p(const unsigned* __restrict__ Wg,
                                            const unsigned* __restrict__ Xg,
                                            const float* __restrict__ bias,
                                            const float* __restrict__ res,
                                            float* __restrict__ out, int O) {
    __shared__ unsigned WpS[2][64 * 20];    // [o][word] stride 20
    __shared__ unsigned XpS[2][128 * 20];   // [t][word] stride 20
    int b  = blockIdx.z;
    int o0 = blockIdx.y << 6, t0 = blockIdx.x << 7;
    int tid = threadIdx.x, lane = tid & 31, warp = tid >> 5;
    int g = lane >> 2, tig = lane & 3;
    int wm = (warp & 3) << 4, wn = (warp >> 2) << 6;
    unsigned wbase = (unsigned)__cvta_generic_to_shared(WpS);
    unsigned xbase = (unsigned)__cvta_generic_to_shared(XpS);
    const unsigned* Xb = Xg + (size_t)b * 128 * Tn;   // [kt][t][16]

    auto issue = [&](int kt, int st) {
        #pragma unroll
        for (int r = 0; r < 3; r++) {
            int e = tid + r * 256;
            if (e < 256) {
                int row = e >> 2, m = e & 3;
                cpa16(wbase + (st * 64 * 20 + row * 20 + m * 4) * 4,
                      Wg + (size_t)(o0 + row) * 128 + kt * 16 + m * 4);
            } else {
                int e2 = e - 256;
                int row = e2 >> 2, m = e2 & 3;
                cpa16(xbase + (st * 128 * 20 + row * 20 + m * 4) * 4,
                      Xb + ((size_t)kt * Tn + t0 + row) * 16 + m * 4);
            }
        }
    };
    issue(0, 0); cpa_commit();
    issue(1, 1); cpa_commit();

    float acc[8][4] = {};
    #pragma unroll 1
    for (int kt = 0; kt < 8; kt++) {
        if (kt < 6) { asm volatile("cp.async.wait_group 1;\n"); }
        else        { asm volatile("cp.async.wait_group 0;\n"); }
        __syncthreads();
        int st = kt & 1;
        unsigned* Wp = WpS[st];
        unsigned xsb = xbase + st * 128 * 20 * 4;
        #pragma unroll
        for (int kb = 0; kb < 16; kb += 8) {
            unsigned A0 = Wp[(wm + g) * 20 + kb + tig];
            unsigned A1 = Wp[(wm + g + 8) * 20 + kb + tig];
            unsigned A2 = Wp[(wm + g) * 20 + kb + tig + 4];
            unsigned A3 = Wp[(wm + g + 8) * 20 + kb + tig + 4];
            unsigned co = (unsigned)((kb >> 3) * 32);
            unsigned B0[8], B1[8];
            ldsm4(B0,     xsb + (wn + lane) * 80 + co);
            ldsm4(B0 + 4, xsb + (wn + 32 + lane) * 80 + co);
            ldsm4(B1,     xsb + (wn + lane) * 80 + co + 16);
            ldsm4(B1 + 4, xsb + (wn + 32 + lane) * 80 + co + 16);
            #pragma unroll
            for (int nf = 0; nf < 8; nf++)
                mma_bf16(acc[nf], A0, A1, A2, A3, B0[nf], B1[nf]);
        }
        __syncthreads();
        if (kt + 2 < 8) { issue(kt + 2, st); cpa_commit(); }
    }

    int o = o0 + wm + g;
    float bv0 = bias[o], bv1 = bias[o + 8];

    if (VSPLIT) {
        int sec = o0 >> 8;                 // 0=Q, 1=K, 2=V
        int h   = (o0 >> 6) & 3;
        int bh  = b * 4 + h;
        if (sec < 2) {
            float scale = (sec == 0) ? 0.125f * 1.44269504f : 1.0f;
            int ge = g & ~1;
            int cp = (wm + ge) >> 1;
            bool evn = (g & 1) == 0;
            #pragma unroll
            for (int nf = 0; nf < 8; nf++) {
                float v0 = (acc[nf][0] + bv0) * scale;
                float v1 = (acc[nf][1] + bv0) * scale;
                float v2 = (acc[nf][2] + bv1) * scale;
                float v3 = (acc[nf][3] + bv1) * scale;
                float u0 = __shfl_xor_sync(0xffffffffu, v0, 4);
                float u1 = __shfl_xor_sync(0xffffffffu, v1, 4);
                float u2 = __shfl_xor_sync(0xffffffffu, v2, 4);
                float u3 = __shfl_xor_sync(0xffffffffu, v3, 4);
                int t = t0 + wn + nf * 8 + tig * 2;
                if (sec == 0) {
                    unsigned* gq = g_qp + (size_t)bh * 32 * Tn;
                    uint2 w;
                    if (evn) {
                        w.x = bf2(v0, u0); w.y = bf2(v1, u1);
                        *(uint2*)(gq + (size_t)cp * Tn + t) = w;
                    } else {
                        w.x = bf2(u2, v2); w.y = bf2(u3, v3);
                        *(uint2*)(gq + (size_t)(cp + 4) * Tn + t) = w;
                    }
                } else {
                    unsigned* gk = g_kp + (size_t)bh * Tn * 32;
                    if (evn) {
                        gk[(size_t)t * 32 + cp]       = bf2(v0, u0);
                        gk[(size_t)(t + 1) * 32 + cp] = bf2(v1, u1);
                    } else {
                        gk[(size_t)t * 32 + cp + 4]       = bf2(u2, v2);
                        gk[(size_t)(t + 1) * 32 + cp + 4] = bf2(u3, v3);
                    }
                }
            }
        } else {
            unsigned* gv = g_vp + (size_t)bh * 64 * (Tn / 2);
            int c = wm + g;
            #pragma unroll
            for (int nf = 0; nf < 8; nf++) {
                int t = t0 + wn + nf * 8 + tig * 2;
                int sp = t >> 1;
                gv[(size_t)c * (Tn / 2) + sp]       = bf2(acc[nf][0] + bv0, acc[nf][1] + bv0);
                gv[(size_t)(c + 8) * (Tn / 2) + sp] = bf2(acc[nf][2] + bv1, acc[nf][3] + bv1);
            }
        }
        return;
    }

    size_t row0 = ((size_t)b * O + o) * Tn + t0;
    size_t row1 = row0 + (size_t)8 * Tn;
    #pragma unroll
    for (int nf = 0; nf < 8; nf++) {
        int t = wn + nf * 8 + tig * 2;
        float2 v0, v1;
        v0.x = acc[nf][0] + bv0 + res[row0 + t];
        v0.y = acc[nf][1] + bv0 + res[row0 + t + 1];
        v1.x = acc[nf][2] + bv1 + res[row1 + t];
        v1.y = acc[nf][3] + bv1 + res[row1 + t + 1];
        *(float2*)(out + row0 + t) = v0;
        *(float2*)(out + row1 + t) = v1;
    }
}

__global__ __launch_bounds__(256) void k_qkv(const float* __restrict__ bias) {
    gemm_body_p<true>(g_wq, g_xp, bias, nullptr, nullptr, 3 * Cn);
}
__global__ __launch_bounds__(256) void k_proj(const float* __restrict__ bias,
                                              const float* __restrict__ res,
                                              float* __restrict__ out) {
    gemm_body_p<false>(g_wp, g_ap, bias, res, out, Cn);
}

// ---------------------------------------------------------------------------
// K4: flash attention (compute core validated R16). TQ=64, 128 thr = 4 warps,
// 4 CTAs/SM, cp.async 3-stage, ldmatrix.x4 B-frags, MUFU-under-tensor
// schedule. Epilogue now writes g_ap in [b][kt][t][16] ldmatrix-row layout.
// ---------------------------------------------------------------------------
constexpr int TQ = 64;
constexpr int STAGE_B = 16384;
constexpr int SMB_Q   = 3 * STAGE_B;
constexpr int ATTN_SMEM_B = SMB_Q + 32 * 64 * 4;   // 57344 B

__global__ __launch_bounds__(128, 4) void k_attn() {
    extern __shared__ __align__(16) unsigned smbuf[];
    unsigned* Qs = smbuf + SMB_Q / 4;          // [cp][t] stride 64

    int bh = blockIdx.y;
    int b = bh >> 2, h = bh & 3;
    int t0 = blockIdx.x * TQ;
    const unsigned* qp = g_qp + (size_t)bh * 32 * Tn;
    const unsigned* kp = g_kp + (size_t)bh * Tn * 32;
    const unsigned* vp = g_vp + (size_t)bh * 64 * (Tn / 2);

    int tid = threadIdx.x;
    int lane = tid & 31, warp = tid >> 5;
    int g = lane >> 2, tig = lane & 3;
    int tm = warp << 4;
    unsigned smem_int = (unsigned)__cvta_generic_to_shared(smbuf);

    #pragma unroll
    for (int r = 0; r < 4; r++) {
        int e = tid + r * 128;
        int cp = e >> 4, ch = (e & 15) << 2;
        cpa16(smem_int + SMB_Q + (cp * 64 + ch) * 4,
              qp + (size_t)cp * Tn + t0 + ch);
    }
    auto issue_tile = [&](int i, int st) {
        unsigned sb = smem_int + st * STAGE_B;
        int s0 = i * 64;
        #pragma unroll
        for (int r = 0; r < 8; r++) {
            int e = tid + r * 128;
            if (e < 512) {
                int row = e >> 3, m = e & 7;
                cpa16(sb + row * 128 + ((m ^ (row & 7)) << 4),
                      kp + (size_t)(s0 + row) * 32 + m * 4);
            } else {
                int e2 = e - 512;
                int c = e2 >> 3, m = e2 & 7;
                cpa16(sb + 8192 + c * 128 + ((m ^ (c & 7)) << 4),
                      vp + (size_t)c * (Tn / 2) + (s0 >> 1) + m * 4);
            }
        }
    };
    issue_tile(0, 0); cpa_commit();
    issue_tile(1, 1); cpa_commit();

    asm volatile("cp.async.wait_group 1;\n");
    __syncthreads();

    unsigned QA[4][4];
    #pragma unroll
    for (int k = 0; k < 4; k++) {
        QA[k][0] = Qs[(8 * k + tig) * 64 + tm + g];
        QA[k][1] = Qs[(8 * k + tig) * 64 + tm + g + 8];
        QA[k][2] = Qs[(8 * k + tig + 4) * 64 + tm + g];
        QA[k][3] = Qs[(8 * k + tig + 4) * 64 + tm + g + 8];
    }

    int lrow = lane & 7;
    unsigned rowoff = (unsigned)((lane >> 3) * 1024 + lrow * 128);
    unsigned mo[4][2];
    #pragma unroll
    for (int k = 0; k < 4; k++) {
        mo[k][0] = (unsigned)(((2 * k)     ^ lrow) << 4);
        mo[k][1] = (unsigned)(((2 * k + 1) ^ lrow) << 4);
    }

    float oacc[8][4] = {};
    float lp0 = 0.f, lp1 = 0.f;

    constexpr int NIT = Tn / 64;
    int st = 0;
    for (int i = 0; i < NIT; i++) {
        if (i > 0) {
            if (i + 1 < NIT) { asm volatile("cp.async.wait_group 1;\n"); }
            else             { asm volatile("cp.async.wait_group 0;\n"); }
            __syncthreads();
        }
        if (i + 2 < NIT) {
            int stn = st + 2; if (stn >= 3) stn -= 3;
            issue_tile(i + 2, stn); cpa_commit();
        }

        unsigned KcI = smem_int + st * STAGE_B;
        unsigned VcI = KcI + 8192;

        // ---- S half0: s-cols 0..31 — pure tensor
        float s0f[4][4] = {};
        #pragma unroll
        for (int k = 0; k < 4; k++) {
            unsigned B0[4], B1[4];
            ldsm4(B0, KcI + rowoff + mo[k][0]);
            ldsm4(B1, KcI + rowoff + mo[k][1]);
            #pragma unroll
            for (int nf = 0; nf < 4; nf++)
                mma_bf16(s0f[nf], QA[k][0], QA[k][1], QA[k][2], QA[k][3],
                         B0[nf], B1[nf]);
        }

        // ---- S half1 interleaved with exp(half0)
        float s1f[4][4] = {};
        unsigned PA[4][4];
        #pragma unroll
        for (int k = 0; k < 4; k++) {
            unsigned B0[4], B1[4];
            ldsm4(B0, KcI + 4096 + rowoff + mo[k][0]);
            ldsm4(B1, KcI + 4096 + rowoff + mo[k][1]);
            float p0 = ex2(s0f[k][0]), p1 = ex2(s0f[k][1]);
            float p2 = ex2(s0f[k][2]), p3 = ex2(s0f[k][3]);
            lp0 += p0 + p1; lp1 += p2 + p3;
            PA[k >> 1][2 * (k & 1)]     = bf2(p0, p1);
            PA[k >> 1][2 * (k & 1) + 1] = bf2(p2, p3);
            #pragma unroll
            for (int nf = 0; nf < 4; nf++)
                mma_bf16(s1f[nf], QA[k][0], QA[k][1], QA[k][2], QA[k][3],
                         B0[nf], B1[nf]);
        }

        // ---- PV chunks 0,1 interleaved with exp(half1)
        #pragma unroll
        for (int k = 0; k < 2; k++) {
            unsigned B0[8], B1[8];
            ldsm4(B0,     VcI + rowoff + mo[k][0]);
            ldsm4(B0 + 4, VcI + rowoff + 4096 + mo[k][0]);
            ldsm4(B1,     VcI + rowoff + mo[k][1]);
            ldsm4(B1 + 4, VcI + rowoff + 4096 + mo[k][1]);
            {
                int j = 2 * k;
                float p0 = ex2(s1f[j][0]), p1 = ex2(s1f[j][1]);
                float p2 = ex2(s1f[j][2]), p3 = ex2(s1f[j][3]);
                float q0 = ex2(s1f[j + 1][0]), q1 = ex2(s1f[j + 1][1]);
                float q2 = ex2(s1f[j + 1][2]), q3 = ex2(s1f[j + 1][3]);
                lp0 += p0 + p1 + q0 + q1;
                lp1 += p2 + p3 + q2 + q3;
                PA[2 + k][0] = bf2(p0, p1);
                PA[2 + k][1] = bf2(p2, p3);
                PA[2 + k][2] = bf2(q0, q1);
                PA[2 + k][3] = bf2(q2, q3);
            }
            #pragma unroll
            for (int nf = 0; nf < 8; nf++)
                mma_bf16(oacc[nf], PA[k][0], PA[k][1], PA[k][2], PA[k][3],
                         B0[nf], B1[nf]);
        }

        // ---- PV chunks 2,3 — pure tensor
        #pragma unroll
        for (int k = 2; k < 4; k++) {
            unsigned B0[8], B1[8];
            ldsm4(B0,     VcI + rowoff + mo[k][0]);
            ldsm4(B0 + 4, VcI + rowoff + 4096 + mo[k][0]);
            ldsm4(B1,     VcI + rowoff + mo[k][1]);
            ldsm4(B1 + 4, VcI + rowoff + 4096 + mo[k][1]);
            #pragma unroll
            for (int nf = 0; nf < 8; nf++)
                mma_bf16(oacc[nf], PA[k][0], PA[k][1], PA[k][2], PA[k][3],
                         B0[nf], B1[nf]);
        }

        st++; if (st >= 3) st = 0;
    }

    lp0 += __shfl_xor_sync(0xffffffffu, lp0, 1);
    lp0 += __shfl_xor_sync(0xffffffffu, lp0, 2);
    lp1 += __shfl_xor_sync(0xffffffffu, lp1, 1);
    lp1 += __shfl_xor_sync(0xffffffffu, lp1, 2);
    float li0 = 1.f / lp0, li1 = 1.f / lp1;

    // normalize, stage [t][word] in smem (stage area is dead), write g_ap
    __syncthreads();
    unsigned* ob = smbuf;                       // [t 64][36]
    #pragma unroll
    for (int nf = 0; nf < 8; nf++) {
        int wofs = 4 * nf + tig;
        ob[(tm + g) * 36 + wofs]     = bf2(oacc[nf][0] * li0, oacc[nf][1] * li0);
        ob[(tm + g + 8) * 36 + wofs] = bf2(oacc[nf][2] * li1, oacc[nf][3] * li1);
    }
    __syncthreads();
    #pragma unroll
    for (int r = 0; r < 4; r++) {
        int e = tid + r * 128;                  // 512 uint4 tasks
        int t = e >> 3, ch = e & 7;
        uint4 v = *(uint4*)&ob[t * 36 + ch * 4];
        int kt = 2 * h + (ch >> 2);
        *(uint4*)(g_ap + (((size_t)b * 8 + kt) * Tn + t0 + t) * 16
                  + (ch & 3) * 4) = v;
    }
}

// ---------------------------------------------------------------------------
extern "C" void kernel_launch(void* const* d_in, const int* in_sizes, int n_in,
                              void* d_out, int out_size) {
    const float* x      = (const float*)d_in[0];
    const float* gn_w   = (const float*)d_in[1];
    const float* gn_b   = (const float*)d_in[2];
    const float* qkv_w  = (const float*)d_in[3];
    const float* qkv_b  = (const float*)d_in[4];
    const float* proj_w = (const float*)d_in[5];
    const float* proj_b = (const float*)d_in[6];
    float* out = (float*)d_out;

    cudaFuncSetAttribute(k_attn, cudaFuncAttributeMaxDynamicSharedMemorySize,
                         ATTN_SMEM_B);

    k_gn_stats<<<4 * 32, 256>>>(x, gn_w, gn_b);
    k_wpack<<<1024, 128>>>(qkv_w, proj_w);
    k_gn_pack<<<dim3(Tn / 128, 8, Bn), 256>>>(x);
    k_qkv <<<dim3(Tn / 128, (3 * Cn) / 64, Bn), 256>>>(qkv_b);
    k_attn<<<dim3(Tn / TQ, Bn * 4), 128, ATTN_SMEM_B>>>();
    k_proj<<<dim3(Tn / 128, Cn / 64, Bn), 256>>>(proj_b, x, out);
}